// round 3
// baseline (speedup 1.0000x reference)
#include <cuda_runtime.h>
#include <cuda_bf16.h>

// Problem shape (fixed by the dataset)
#define N_DIM 8
#define V_DIM 3
#define C_DIM 24
#define T_DIM 8
#define H_DIM 128
#define W_DIM 128

constexpr int HW      = H_DIM * W_DIM;         // 16384
constexpr int VCT     = V_DIM * C_DIM * T_DIM; // 576 slabs per n
constexpr int CHUNK   = 2048;                  // hw positions per block
constexpr int NCHUNK  = HW / CHUNK;            // 8
constexpr int GROUP   = 48;                    // slabs per block
constexpr int NGROUP  = VCT / GROUP;           // 12
constexpr int MAIN_BLOCKS  = N_DIM * NCHUNK * NGROUP; // 768
constexpr int TOTAL_BLOCKS = MAIN_BLOCKS + N_DIM;     // +8 mask-sum blocks
constexpr int THREADS = 256;
constexpr int F4_PER_THREAD = CHUNK / 4 / THREADS;    // 2

// Deterministic reduction scratch (static device globals — no allocation)
__device__ float g_part[MAIN_BLOCKS];
__device__ float g_maskpart[N_DIM];
__device__ unsigned int g_count = 0;   // completion counter (reset by finisher)

__global__ __launch_bounds__(THREADS)
void anomaly_l1_fused(const float* __restrict__ pred,
                      const int*   __restrict__ mask,
                      const float* __restrict__ vq0,
                      float* __restrict__ out)
{
    __shared__ float sw[CHUNK];            // weights (1 - mask) for this hw-chunk
    __shared__ float sred[THREADS / 32];
    __shared__ unsigned int s_isLast;

    const int b   = blockIdx.x;
    const int tid = threadIdx.x;

    if (b >= MAIN_BLOCKS) {
        // ---- tail blocks: per-n mask sums (denominator) ----
        const int n = b - MAIN_BLOCKS;
        const int4* m4 = reinterpret_cast<const int4*>(mask + n * HW);
        int s = 0;
        #pragma unroll
        for (int k = 0; k < HW / 4 / THREADS; ++k) {   // 16 int4 per thread
            int4 v = m4[tid + k * THREADS];
            s += v.x + v.y + v.z + v.w;
        }
        #pragma unroll
        for (int o = 16; o; o >>= 1) s += __shfl_xor_sync(0xFFFFFFFFu, s, o);
        if ((tid & 31) == 0) sred[tid >> 5] = (float)s;
        __syncthreads();
        if (tid == 0) {
            float t = 0.f;
            #pragma unroll
            for (int i = 0; i < THREADS / 32; ++i) t += sred[i];
            g_maskpart[n] = t;
        }
    } else {
        // ---- main blocks: decode (n, chunk, group) ----
        const int group = b % NGROUP;
        const int chunk = (b / NGROUP) % NCHUNK;
        const int n     = b / (NGROUP * NCHUNK);

        // Stage weights into SMEM once; reused across GROUP=48 slabs.
        {
            const int4* m4 = reinterpret_cast<const int4*>(mask + n * HW + chunk * CHUNK);
            #pragma unroll
            for (int k = 0; k < F4_PER_THREAD; ++k) {
                int4 v = m4[tid + k * THREADS];
                float4 w = make_float4(1.f - (float)v.x, 1.f - (float)v.y,
                                       1.f - (float)v.z, 1.f - (float)v.w);
                reinterpret_cast<float4*>(sw)[tid + k * THREADS] = w;
            }
        }
        __syncthreads();

        const int slab0 = group * GROUP;
        const float* base = pred + ((size_t)n * VCT + slab0) * (size_t)HW
                                 + (size_t)chunk * CHUNK;

        float acc = 0.f;
        #pragma unroll 4
        for (int s = 0; s < GROUP; ++s) {
            const int slab = slab0 + s;
            const int c = (slab >> 3) % C_DIM;     // T=8 → t is low 3 bits
            const float vq = __ldg(vq0 + c);
            const float4* p = reinterpret_cast<const float4*>(base + (size_t)s * HW);
            #pragma unroll
            for (int k = 0; k < F4_PER_THREAD; ++k) {
                float4 x = p[tid + k * THREADS];
                float4 w = reinterpret_cast<const float4*>(sw)[tid + k * THREADS];
                acc = fmaf(fabsf(x.x - vq), w.x, acc);
                acc = fmaf(fabsf(x.y - vq), w.y, acc);
                acc = fmaf(fabsf(x.z - vq), w.z, acc);
                acc = fmaf(fabsf(x.w - vq), w.w, acc);
            }
        }

        #pragma unroll
        for (int o = 16; o; o >>= 1) acc += __shfl_xor_sync(0xFFFFFFFFu, acc, o);
        if ((tid & 31) == 0) sred[tid >> 5] = acc;
        __syncthreads();
        if (tid == 0) {
            float t = 0.f;
            #pragma unroll
            for (int i = 0; i < THREADS / 32; ++i) t += sred[i];
            g_part[b] = t;
        }
    }

    // ---- last-block-finishes: deterministic final reduction ----
    // The atomic only ELECTS the finisher; the summation itself walks
    // g_part[] in fixed index order, so the result is bit-deterministic.
    if (tid == 0) {
        __threadfence();
        unsigned int prev = atomicAdd(&g_count, 1u);
        s_isLast = (prev == TOTAL_BLOCKS - 1u) ? 1u : 0u;
    }
    __syncthreads();
    if (s_isLast) {
        float a = 0.f;
        for (int i = tid; i < MAIN_BLOCKS; i += THREADS) a += g_part[i];
        #pragma unroll
        for (int o = 16; o; o >>= 1) a += __shfl_xor_sync(0xFFFFFFFFu, a, o);
        if ((tid & 31) == 0) sred[tid >> 5] = a;
        __syncthreads();
        if (tid == 0) {
            float num = 0.f;
            #pragma unroll
            for (int i = 0; i < THREADS / 32; ++i) num += sred[i];
            float msum = 0.f;
            #pragma unroll
            for (int i = 0; i < N_DIM; ++i) msum += g_maskpart[i];
            double sumw = (double)N_DIM * HW - (double)msum;  // sum of weights over (N,H,W)
            double den  = sumw * (double)VCT;
            out[0] = (float)((double)num / den);
            g_count = 0;   // reset for next graph replay
        }
    }
}

extern "C" void kernel_launch(void* const* d_in, const int* in_sizes, int n_in,
                              void* d_out, int out_size)
{
    const float* pred = (const float*)d_in[0];   // (N,V,C,T,H,W) fp32
    const int*   mask = (const int*)  d_in[1];   // (N,H,W) int32
    const float* vq0  = (const float*)d_in[2];   // (1,C) fp32
    float* out = (float*)d_out;

    anomaly_l1_fused<<<TOTAL_BLOCKS, THREADS>>>(pred, mask, vq0, out);
}

// round 5
// speedup vs baseline: 1.1199x; 1.1199x over previous
#include <cuda_runtime.h>
#include <cuda_bf16.h>

// Problem shape (fixed by the dataset)
#define N_DIM 8
#define V_DIM 3
#define C_DIM 24
#define T_DIM 8
#define H_DIM 128
#define W_DIM 128

constexpr int HW      = H_DIM * W_DIM;         // 16384
constexpr int VCT     = V_DIM * C_DIM * T_DIM; // 576 slabs per n
constexpr int CHUNK   = 2048;                  // hw positions per block
constexpr int NCHUNK  = HW / CHUNK;            // 8
constexpr int GROUP   = 48;                    // slabs per block
constexpr int NGROUP  = VCT / GROUP;           // 12
constexpr int MAIN_BLOCKS  = N_DIM * NCHUNK * NGROUP; // 768
constexpr int TOTAL_BLOCKS = MAIN_BLOCKS + N_DIM;     // +8 mask-sum blocks
constexpr int THREADS = 256;
constexpr int F4_PER_THREAD = CHUNK / 4 / THREADS;    // 2

// Deterministic reduction scratch (static device globals — no allocation)
__device__ float g_part[MAIN_BLOCKS];
__device__ float g_maskpart[N_DIM];

__global__ __launch_bounds__(THREADS)
void anomaly_l1_main(const float* __restrict__ pred,
                     const int*   __restrict__ mask,
                     const float* __restrict__ vq0)
{
    __shared__ float sw[CHUNK];            // weights (1 - mask) for this hw-chunk
    __shared__ float sred[THREADS / 32];

    const int b   = blockIdx.x;
    const int tid = threadIdx.x;

    if (b >= MAIN_BLOCKS) {
        // ---- tail blocks: per-n mask sums (denominator) ----
        const int n = b - MAIN_BLOCKS;
        const int4* m4 = reinterpret_cast<const int4*>(mask + n * HW);
        int s = 0;
        #pragma unroll
        for (int k = 0; k < HW / 4 / THREADS; ++k) {   // 16 int4 per thread
            int4 v = m4[tid + k * THREADS];
            s += v.x + v.y + v.z + v.w;
        }
        #pragma unroll
        for (int o = 16; o; o >>= 1) s += __shfl_xor_sync(0xFFFFFFFFu, s, o);
        if ((tid & 31) == 0) sred[tid >> 5] = (float)s;
        __syncthreads();
        if (tid == 0) {
            float t = 0.f;
            #pragma unroll
            for (int i = 0; i < THREADS / 32; ++i) t += sred[i];
            g_maskpart[n] = t;
        }
        // Let the dependent (PDL) final kernel begin its launch ramp.
        cudaTriggerProgrammaticLaunchCompletion();
        return;
    }

    // ---- main blocks: decode (n, chunk, group) ----
    const int group = b % NGROUP;
    const int chunk = (b / NGROUP) % NCHUNK;
    const int n     = b / (NGROUP * NCHUNK);

    // Stage weights into SMEM once; reused across GROUP=48 slabs.
    {
        const int4* m4 = reinterpret_cast<const int4*>(mask + n * HW + chunk * CHUNK);
        #pragma unroll
        for (int k = 0; k < F4_PER_THREAD; ++k) {
            int4 v = m4[tid + k * THREADS];
            float4 w = make_float4(1.f - (float)v.x, 1.f - (float)v.y,
                                   1.f - (float)v.z, 1.f - (float)v.w);
            reinterpret_cast<float4*>(sw)[tid + k * THREADS] = w;
        }
    }
    __syncthreads();

    const int slab0 = group * GROUP;
    const float* base = pred + ((size_t)n * VCT + slab0) * (size_t)HW
                             + (size_t)chunk * CHUNK;

    float acc = 0.f;
    #pragma unroll 4
    for (int s = 0; s < GROUP; ++s) {
        const int slab = slab0 + s;
        const int c = (slab >> 3) % C_DIM;     // T=8 → t is low 3 bits
        const float vq = __ldg(vq0 + c);
        const float4* p = reinterpret_cast<const float4*>(base + (size_t)s * HW);
        #pragma unroll
        for (int k = 0; k < F4_PER_THREAD; ++k) {
            float4 x = p[tid + k * THREADS];
            float4 w = reinterpret_cast<const float4*>(sw)[tid + k * THREADS];
            acc = fmaf(fabsf(x.x - vq), w.x, acc);
            acc = fmaf(fabsf(x.y - vq), w.y, acc);
            acc = fmaf(fabsf(x.z - vq), w.z, acc);
            acc = fmaf(fabsf(x.w - vq), w.w, acc);
        }
    }

    #pragma unroll
    for (int o = 16; o; o >>= 1) acc += __shfl_xor_sync(0xFFFFFFFFu, acc, o);
    if ((tid & 31) == 0) sred[tid >> 5] = acc;
    __syncthreads();
    if (tid == 0) {
        float t = 0.f;
        #pragma unroll
        for (int i = 0; i < THREADS / 32; ++i) t += sred[i];
        g_part[b] = t;
    }
    cudaTriggerProgrammaticLaunchCompletion();
}

__global__ __launch_bounds__(THREADS)
void anomaly_l1_final(float* __restrict__ out)
{
    __shared__ float sred[THREADS / 32];
    const int tid = threadIdx.x;

    // PDL: wait for the main kernel to fully complete (ordering + visibility)
    // before consuming its partials. Everything above this line overlaps the
    // main kernel's tail.
    cudaGridDependencySynchronize();

    float a = 0.f;
    for (int i = tid; i < MAIN_BLOCKS; i += THREADS) a += g_part[i];
    #pragma unroll
    for (int o = 16; o; o >>= 1) a += __shfl_xor_sync(0xFFFFFFFFu, a, o);
    if ((tid & 31) == 0) sred[tid >> 5] = a;
    __syncthreads();
    if (tid == 0) {
        float num = 0.f;
        #pragma unroll
        for (int i = 0; i < THREADS / 32; ++i) num += sred[i];
        float msum = 0.f;
        #pragma unroll
        for (int i = 0; i < N_DIM; ++i) msum += g_maskpart[i];
        double sumw = (double)N_DIM * HW - (double)msum;  // sum of weights over (N,H,W)
        double den  = sumw * (double)VCT;
        out[0] = (float)((double)num / den);
    }
}

extern "C" void kernel_launch(void* const* d_in, const int* in_sizes, int n_in,
                              void* d_out, int out_size)
{
    const float* pred = (const float*)d_in[0];   // (N,V,C,T,H,W) fp32
    const int*   mask = (const int*)  d_in[1];   // (N,H,W) int32
    const float* vq0  = (const float*)d_in[2];   // (1,C) fp32
    float* out = (float*)d_out;

    anomaly_l1_main<<<TOTAL_BLOCKS, THREADS>>>(pred, mask, vq0);

    // Launch the reduction tail with Programmatic Dependent Launch so its
    // launch latency overlaps the main kernel's final wave.
    cudaLaunchConfig_t cfg = {};
    cfg.gridDim  = dim3(1, 1, 1);
    cfg.blockDim = dim3(THREADS, 1, 1);
    cfg.dynamicSmemBytes = 0;
    cfg.stream = 0;   // same (capturing) stream as the <<<>>> launch above
    cudaLaunchAttribute attr[1];
    attr[0].id = cudaLaunchAttributeProgrammaticStreamSerialization;
    attr[0].val.programmaticStreamSerializationAllowed = 1;
    cfg.attrs = attr;
    cfg.numAttrs = 1;
    cudaError_t e = cudaLaunchKernelEx(&cfg, anomaly_l1_final, out);
    if (e != cudaSuccess) {
        // Fallback: plain dependent launch (keeps correctness if PDL is
        // unavailable under this capture mode).
        anomaly_l1_final<<<1, THREADS>>>(out);
    }
}